// round 4
// baseline (speedup 1.0000x reference)
#include <cuda_runtime.h>
#include <cuda_fp16.h>
#include <math.h>

#define HH    14
#define WW    14
#define NN    197
#define BB    8
#define DIMV  64
#define NHEAD 2
#define DH    32
#define NUU   1122
#define NPAIR (NN*NN)   // 38809
#define RELPAIRS 38416
#define RELU_ 729
#define WLMAX 4096
#define NATTNBLK 400
#define SCALE 0.17677669529663687f
#define SMEM_MAIN 55296   // sU(2x64x72 half)=18432B + sA(8x2x16x72 half)=36864B

// ---------------- scratch -------------------------------------------------------
__device__ float    g_xn[BB*NN*DIMV];
__device__ float    g_qk[BB*NN*2*DIMV];
__device__ float    g_attn[BB*NHEAD*NN*NN];
__device__ __half   g_T[(size_t)NPAIR*BB*DIMV];   // 39.7 MB  T[n,m,b,e] fp16
__device__ unsigned g_pairs[NPAIR];
__device__ uint2    g_work[WLMAX];
__device__ int      g_nwork;

__device__ __forceinline__ int hfun(int a) { return 14 - abs(a - 13); }
__device__ __forceinline__ int cfun(int t) {
    return (t <= 13) ? (t*(t+1))/2 : 196 - ((27-t)*(28-t))/2;
}
__device__ __forceinline__ unsigned h2u(__half2 h) { return *reinterpret_cast<unsigned*>(&h); }

#define LDSM4(r, addr) \
    asm volatile("ldmatrix.sync.aligned.m8n8.x4.shared.b16 {%0,%1,%2,%3}, [%4];" \
        : "=r"((r)[0]), "=r"((r)[1]), "=r"((r)[2]), "=r"((r)[3]) : "r"(addr))
#define LDSM4T(r, addr) \
    asm volatile("ldmatrix.sync.aligned.m8n8.x4.trans.shared.b16 {%0,%1,%2,%3}, [%4];" \
        : "=r"((r)[0]), "=r"((r)[1]), "=r"((r)[2]), "=r"((r)[3]) : "r"(addr))
#define MMA16816(c, a, b0v, b1v) \
    asm volatile("mma.sync.aligned.m16n8k16.row.col.f32.f16.f16.f32 " \
        "{%0,%1,%2,%3},{%4,%5,%6,%7},{%8,%9},{%0,%1,%2,%3};" \
        : "+f"((c)[0]), "+f"((c)[1]), "+f"((c)[2]), "+f"((c)[3]) \
        : "r"((a)[0]), "r"((a)[1]), "r"((a)[2]), "r"((a)[3]), "r"(b0v), "r"(b1v))

// ================= setup kernel: fill | plan | LN+QK ===========================
__global__ void __launch_bounds__(256) k_setup(const float* __restrict__ x,
                                               const float* __restrict__ gamma,
                                               const float* __restrict__ beta,
                                               const float* __restrict__ wqk) {
    __shared__ union {
        struct { int sa[2048]; int sb[2048]; } plan;
        struct { float sxn[BB][DIMV]; float part[2][128][BB]; } ln;
    } sm;
    int bid = blockIdx.x, t = threadIdx.x;

    if (bid < 152) {
        int i = bid*256 + t;
        if (i >= NPAIR) return;
        int n = i / NN, m = i % NN;
        int pos;
        if (n == 0)      pos = RELPAIRS + m;
        else if (m == 0) pos = RELPAIRS + NN + (n - 1);
        else {
            int xx = (n-1) / WW, yy = (n-1) % WW;
            int ii = (m-1) / WW, jj = (m-1) % WW;
            int dx = xx - ii + 13, dy = yy - jj + 13;
            int off = cfun(dx)*196 + hfun(dx)*cfun(dy);
            int xmin = max(0, dx-13), ymin = max(0, dy-13);
            pos = off + (xx - xmin)*hfun(dy) + (yy - ymin);
        }
        g_pairs[pos] = ((unsigned)n << 16) | (unsigned)m;
        return;
    }
    if (bid == 152) {
        int *src = sm.plan.sa, *dst = sm.plan.sb;
        for (int i = t; i < 2048; i += 256) {
            int c = 0;
            if (i < RELU_)    c = hfun(i/27) * hfun(i%27);
            else if (i < NUU) c = 1;
            src[i] = (c + 15) >> 4;
        }
        __syncthreads();
        for (int off = 1; off < 2048; off <<= 1) {
            for (int i = t; i < 2048; i += 256)
                dst[i] = src[i] + (i >= off ? src[i-off] : 0);
            __syncthreads();
            int* tmp = src; src = dst; dst = tmp;
        }
        for (int u = t; u < NUU; u += 256) {
            int cnt, po;
            if (u < RELU_) {
                int dx = u/27, dy = u%27;
                cnt = hfun(dx)*hfun(dy);
                po  = cfun(dx)*196 + hfun(dx)*cfun(dy);
            } else if (u < RELU_ + NN) { cnt = 1; po = RELPAIRS + (u - RELU_); }
            else                       { cnt = 1; po = RELPAIRS + NN + (u - RELU_ - NN); }
            int eo = (u == 0) ? 0 : src[u-1];
            int j = 0;
            for (int s = 0; s < cnt; s += 16, j++) {
                int c = cnt - s; if (c > 16) c = 16;
                if (eo + j < WLMAX)
                    g_work[eo + j] = make_uint2((unsigned)(po + s),
                                                ((unsigned)u << 16) | (unsigned)c);
            }
        }
        if (t == 0) g_nwork = min(src[NUU-1], WLMAX);
        return;
    }

    // ---- LN + QK : one block per token n, all 8 batches ----
    int n = bid - 153;
    int w = t >> 5, lane = t & 31;
    {
        const float* xr = x + ((size_t)(w*NN + n))*DIMV;
        float2 v = *(const float2*)(xr + 2*lane);
        float sum = v.x + v.y, sq = v.x*v.x + v.y*v.y;
        #pragma unroll
        for (int o = 16; o > 0; o >>= 1) {
            sum += __shfl_xor_sync(0xffffffffu, sum, o);
            sq  += __shfl_xor_sync(0xffffffffu, sq,  o);
        }
        float mu  = sum * (1.0f/DIMV);
        float var = sq  * (1.0f/DIMV) - mu*mu;
        float r   = rsqrtf(var + 1e-5f);
        float2 o2;
        o2.x = (v.x - mu) * r * gamma[2*lane]   + beta[2*lane];
        o2.y = (v.y - mu) * r * gamma[2*lane+1] + beta[2*lane+1];
        sm.ln.sxn[w][2*lane]   = o2.x;
        sm.ln.sxn[w][2*lane+1] = o2.y;
        *(float2*)(g_xn + ((size_t)(w*NN + n))*DIMV + 2*lane) = o2;
    }
    __syncthreads();
    int c = t & 127, half_ = t >> 7;
    float acc[BB];
    #pragma unroll
    for (int b = 0; b < BB; b++) acc[b] = 0.f;
    int d0 = half_ * 32;
    #pragma unroll 8
    for (int d = 0; d < 32; d++) {
        float wv = wqk[(d0 + d)*128 + c];
        #pragma unroll
        for (int b = 0; b < BB; b++) acc[b] += sm.ln.sxn[b][d0 + d] * wv;
    }
    #pragma unroll
    for (int b = 0; b < BB; b++) sm.ln.part[half_][c][b] = acc[b];
    __syncthreads();
    if (half_ == 0) {
        #pragma unroll
        for (int b = 0; b < BB; b++) {
            float v = sm.ln.part[0][c][b] + sm.ln.part[1][c][b];
            g_qk[((size_t)(b*NN + n))*128 + c] = v;
        }
    }
}

// ================= main kernel: attn [0,400) | tensor pair GEMM [400,...) ======
__global__ void __launch_bounds__(256) k_mainattn(const float* __restrict__ up) {
    extern __shared__ __align__(16) char smx[];
    int bid = blockIdx.x;
    int tid = threadIdx.x, lane = tid & 31, w = tid >> 5;

    if (bid < NATTNBLK) {
        // ---------------- attention scores + softmax ----------------
        float* ks_s = (float*)smx;                 // NN*33
        float* qs_s = ks_s + NN*33;                // DH
        float* red  = qs_s + DH;                   // 8
        float* bc   = red + 8;                     // 1
        int b  = bid / (NHEAD*25);
        int r  = bid % (NHEAD*25);
        int h  = r / 25;
        int nt = r % 25;
        for (int i = tid; i < NN*DH; i += 256) {
            int m = i >> 5, d = i & 31;
            ks_s[m*33 + d] = g_qk[(b*NN + m)*128 + 64 + h*DH + d];
        }
        __syncthreads();
        for (int k0 = 0; k0 < 8; k0++) {
            int n = nt*8 + k0;
            if (n >= NN) break;
            if (tid < DH) qs_s[tid] = g_qk[(b*NN + n)*128 + h*DH + tid];
            __syncthreads();
            float s = -3.0e38f;
            if (tid < NN) {
                float a = 0.f;
                #pragma unroll 8
                for (int d = 0; d < DH; d++) a += qs_s[d] * ks_s[tid*33 + d];
                s = a * SCALE;
            }
            float loc = s;
            #pragma unroll
            for (int o = 16; o > 0; o >>= 1) loc = fmaxf(loc, __shfl_xor_sync(0xffffffffu, loc, o));
            if (lane == 0) red[w] = loc;
            __syncthreads();
            if (tid == 0) {
                float m0 = red[0];
                #pragma unroll
                for (int i = 1; i < 8; i++) m0 = fmaxf(m0, red[i]);
                bc[0] = m0;
            }
            __syncthreads();
            float mx = bc[0];
            float p = (tid < NN) ? __expf(s - mx) : 0.f;
            float ls = p;
            #pragma unroll
            for (int o = 16; o > 0; o >>= 1) ls += __shfl_xor_sync(0xffffffffu, ls, o);
            if (lane == 0) red[w] = ls;
            __syncthreads();
            if (tid == 0) {
                float s0 = 0.f;
                #pragma unroll
                for (int i = 0; i < 8; i++) s0 += red[i];
                bc[0] = s0;
            }
            __syncthreads();
            float inv = 1.0f / bc[0];
            if (tid < NN) g_attn[(((size_t)b*NHEAD + h)*NN + n)*NN + tid] = p * inv;
            __syncthreads();
        }
        return;
    }

    // -------- tensor-core pair GEMM: T[n,m,b,:] = xn[b,m] . U[u] (fp16 3-pass) --
    int wid_ = bid - NATTNBLK;
    if (wid_ >= g_nwork) return;
    uint2 wk = g_work[wid_];
    int pairStart = (int)wk.x;
    int u   = (int)(wk.y >> 16);
    int cnt = (int)(wk.y & 0xffffu);

    __half* sUh = (__half*)smx;              // [64][72]
    __half* sUl = sUh + 64*72;               // [64][72]
    __half* sA0 = sUl + 64*72;               // 8 warps x (hi[16][72] + lo[16][72])

    const float* Up = up + (size_t)u * 4096;
    for (int i = tid; i < 4096; i += 256) {
        float v = Up[i];
        __half hi = __float2half_rn(v);
        __half lo = __float2half_rn(v - __half2float(hi));
        int d = i >> 6, e = i & 63;
        sUh[d*72 + e] = hi;
        sUl[d*72 + e] = lo;
    }
    __syncthreads();

    int p0 = 2*w, p1 = 2*w + 1;
    if (p0 >= cnt) return;
    bool have1 = (p1 < cnt);
    unsigned pk0 = g_pairs[pairStart + p0];
    unsigned pk1 = g_pairs[pairStart + (have1 ? p1 : p0)];
    int n0 = (int)(pk0 >> 16), m0 = (int)(pk0 & 0xffffu);
    int n1 = (int)(pk1 >> 16), m1 = (int)(pk1 & 0xffffu);

    __half* sAh = sA0 + w*2304;              // [16][72]
    __half* sAl = sAh + 1152;

    // ---- stage A: rows r = pair*8 + batch, cols = d (hi/lo split) ----
    {
        int r = lane >> 1, hsel = lane & 1;
        int pr = r >> 3, b = r & 7;
        int mm = pr ? m1 : m0;
        const float4* src = (const float4*)(g_xn + (b*NN + mm)*DIMV + hsel*32);
        uint4* dsth = (uint4*)(sAh + r*72 + hsel*32);
        uint4* dstl = (uint4*)(sAl + r*72 + hsel*32);
        #pragma unroll
        for (int j = 0; j < 4; j++) {
            float4 v0 = src[2*j], v1 = src[2*j+1];
            __half2 h0 = __floats2half2_rn(v0.x, v0.y), h1 = __floats2half2_rn(v0.z, v0.w);
            __half2 h2 = __floats2half2_rn(v1.x, v1.y), h3 = __floats2half2_rn(v1.z, v1.w);
            float2 f0 = __half22float2(h0), f1 = __half22float2(h1);
            float2 f2 = __half22float2(h2), f3 = __half22float2(h3);
            __half2 l0 = __floats2half2_rn(v0.x - f0.x, v0.y - f0.y);
            __half2 l1 = __floats2half2_rn(v0.z - f1.x, v0.w - f1.y);
            __half2 l2 = __floats2half2_rn(v1.x - f2.x, v1.y - f2.y);
            __half2 l3 = __floats2half2_rn(v1.z - f3.x, v1.w - f3.y);
            dsth[j] = make_uint4(h2u(h0), h2u(h1), h2u(h2), h2u(h3));
            dstl[j] = make_uint4(h2u(l0), h2u(l1), h2u(l2), h2u(l3));
        }
    }
    __syncwarp();

    unsigned uAh = (unsigned)__cvta_generic_to_shared(sAh);
    unsigned uAl = (unsigned)__cvta_generic_to_shared(sAl);
    unsigned uUh = (unsigned)__cvta_generic_to_shared(sUh);
    unsigned uUl = (unsigned)__cvta_generic_to_shared(sUl);

    int t15   = lane & 15;
    int col8  = (lane < 16) ? 0 : 8;
    unsigned aoffs = (unsigned)(t15*144 + col8*2);
    unsigned boffs = aoffs;   // same structure: row (t&15)*144 + col8*2

    float acc[8][4];
    #pragma unroll
    for (int i = 0; i < 8; i++)
        #pragma unroll
        for (int j = 0; j < 4; j++) acc[i][j] = 0.f;

    #pragma unroll
    for (int ks = 0; ks < 4; ks++) {
        unsigned ah[4], al[4];
        LDSM4(ah, uAh + aoffs + ks*32);
        LDSM4(al, uAl + aoffs + ks*32);
        #pragma unroll
        for (int ntp = 0; ntp < 4; ntp++) {
            unsigned bh[4], bl[4];
            unsigned bo = boffs + ks*2304 + ntp*32;
            LDSM4T(bh, uUh + bo);
            LDSM4T(bl, uUl + bo);
            MMA16816(acc[2*ntp],   ah, bh[0], bh[1]);
            MMA16816(acc[2*ntp],   al, bh[0], bh[1]);
            MMA16816(acc[2*ntp],   ah, bl[0], bl[1]);
            MMA16816(acc[2*ntp+1], ah, bh[2], bh[3]);
            MMA16816(acc[2*ntp+1], al, bh[2], bh[3]);
            MMA16816(acc[2*ntp+1], ah, bl[2], bl[3]);
        }
    }

    // ---- store: D rows g -> pair0 batch g, rows g+8 -> pair1 batch g ----
    int g  = lane >> 2;
    int t4 = lane & 3;
    size_t base0 = ((size_t)(n0*NN + m0))*512 + g*64;
    size_t base1 = ((size_t)(n1*NN + m1))*512 + g*64;
    #pragma unroll
    for (int nt = 0; nt < 8; nt++) {
        int e = nt*8 + 2*t4;
        __half2 v0 = __floats2half2_rn(acc[nt][0], acc[nt][1]);
        *(__half2*)&g_T[base0 + e] = v0;
        if (have1) {
            __half2 v1 = __floats2half2_rn(acc[nt][2], acc[nt][3]);
            *(__half2*)&g_T[base1 + e] = v1;
        }
    }
}

// ================= phase 2: attn-weighted sum + output projection ==============
__global__ void __launch_bounds__(256) k_out(const float* __restrict__ wout,
                                             const float* __restrict__ bout,
                                             float* __restrict__ out) {
    __shared__ float sA[2*200];
    __shared__ float2 sRed[8][32];
    __shared__ float sAcc[DIMV];
    int bid = blockIdx.x;
    int b = bid / NN, n = bid % NN;
    int t = threadIdx.x;
    int p = t & 31, q = t >> 5;
    for (int i = t; i < 2*NN; i += 256) {
        int h = i / NN, m = i % NN;
        sA[h*200 + m] = g_attn[(((size_t)b*NHEAD + h)*NN + n)*NN + m];
    }
    __syncthreads();
    int e = 2*p;
    int h = e >> 5;
    const __half2* Tb = (const __half2*)(g_T + (size_t)(n*NN)*(BB*DIMV) + b*DIMV + e);
    float2 acc; acc.x = 0.f; acc.y = 0.f;
    for (int m = q; m < NN; m += 8) {
        float a = sA[h*200 + m];
        float2 v = __half22float2(Tb[(size_t)m * (BB*DIMV/2)]);
        acc.x += a * v.x;
        acc.y += a * v.y;
    }
    sRed[q][p] = acc;
    __syncthreads();
    if (t < 32) {
        float2 s = sRed[0][t];
        #pragma unroll
        for (int j = 1; j < 8; j++) { s.x += sRed[j][t].x; s.y += sRed[j][t].y; }
        sAcc[2*t] = s.x; sAcc[2*t+1] = s.y;
    }
    __syncthreads();
    if (t < DIMV) {
        float r = bout[t];
        #pragma unroll 8
        for (int k = 0; k < DIMV; k++) r += sAcc[k] * wout[k*DIMV + t];
        out[((size_t)(b*NN + n))*DIMV + t] = r;
    }
}

// ---------------- launch -------------------------------------------------------
extern "C" void kernel_launch(void* const* d_in, const int* in_sizes, int n_in,
                              void* d_out, int out_size) {
    const float* x     = (const float*)d_in[0];
    const float* gamma = (const float*)d_in[1];
    const float* beta  = (const float*)d_in[2];
    const float* wqk   = (const float*)d_in[3];
    const float* up    = (const float*)d_in[4];
    const float* wout  = (const float*)d_in[5];
    const float* bout  = (const float*)d_in[6];
    float* out = (float*)d_out;

    cudaFuncSetAttribute(k_mainattn, cudaFuncAttributeMaxDynamicSharedMemorySize, SMEM_MAIN);

    k_setup   <<<153 + NN, 256>>>(x, gamma, beta, wqk);
    k_mainattn<<<NATTNBLK + WLMAX, 256, SMEM_MAIN>>>(up);
    k_out     <<<BB*NN, 256>>>(wout, bout, out);
}

// round 6
// speedup vs baseline: 1.3716x; 1.3716x over previous
#include <cuda_runtime.h>
#include <cuda_fp16.h>
#include <math.h>

#define HH    14
#define WW    14
#define NN    197
#define BB    8
#define DIMV  64
#define NHEAD 2
#define DH    32
#define NUU   1122
#define NPAIR (NN*NN)   // 38809
#define RELPAIRS 38416
#define RELU_ 729
#define WLMAX 4096
#define NATTNBLK 400
#define SCALE 0.17677669529663687f
#define SMEM_MAIN 49152   // sU 16KB + sXT 32KB

typedef unsigned long long ull;

// ---------------- scratch -------------------------------------------------------
__device__ float    g_xn[BB*NN*DIMV];
__device__ float    g_qk[BB*NN*2*DIMV];
__device__ float    g_attn[BB*NHEAD*NN*NN];
__device__ __half   g_T[(size_t)NPAIR*BB*DIMV];   // 39.7 MB  T[n,m,b,e] fp16
__device__ unsigned g_pairs[NPAIR];
__device__ uint2    g_work[WLMAX];
__device__ int      g_nwork;

__device__ __forceinline__ int hfun(int a) { return 14 - abs(a - 13); }
__device__ __forceinline__ int cfun(int t) {
    return (t <= 13) ? (t*(t+1))/2 : 196 - ((27-t)*(28-t))/2;
}
__device__ __forceinline__ unsigned h2u(__half2 h) { return *reinterpret_cast<unsigned*>(&h); }

#define FMA2(acc, a, b) asm("fma.rn.f32x2 %0, %1, %2, %0;" : "+l"(acc) : "l"(a), "l"(b))
#define DUP2(dst, s)    asm("mov.b64 %0, {%1, %1};" : "=l"(dst) : "r"(__float_as_uint(s)))
#define UNPK(lo, hi, v) asm("mov.b64 {%0,%1}, %2;" : "=r"(lo), "=r"(hi) : "l"(v))

// ================= setup kernel: fill | plan | LN+QK ===========================
__global__ void __launch_bounds__(256) k_setup(const float* __restrict__ x,
                                               const float* __restrict__ gamma,
                                               const float* __restrict__ beta,
                                               const float* __restrict__ wqk) {
    __shared__ union {
        struct { int sa[2048]; int sb[2048]; } plan;
        struct { float sxn[BB][DIMV]; float part[2][128][BB]; } ln;
    } sm;
    int bid = blockIdx.x, t = threadIdx.x;

    if (bid < 152) {
        int i = bid*256 + t;
        if (i >= NPAIR) return;
        int n = i / NN, m = i % NN;
        int pos;
        if (n == 0)      pos = RELPAIRS + m;
        else if (m == 0) pos = RELPAIRS + NN + (n - 1);
        else {
            int xx = (n-1) / WW, yy = (n-1) % WW;
            int ii = (m-1) / WW, jj = (m-1) % WW;
            int dx = xx - ii + 13, dy = yy - jj + 13;
            int off = cfun(dx)*196 + hfun(dx)*cfun(dy);
            int xmin = max(0, dx-13), ymin = max(0, dy-13);
            pos = off + (xx - xmin)*hfun(dy) + (yy - ymin);
        }
        g_pairs[pos] = ((unsigned)n << 16) | (unsigned)m;
        return;
    }
    if (bid == 152) {
        int *src = sm.plan.sa, *dst = sm.plan.sb;
        for (int i = t; i < 2048; i += 256) {
            int c = 0;
            if (i < RELU_)    c = hfun(i/27) * hfun(i%27);
            else if (i < NUU) c = 1;
            src[i] = (c + 15) >> 4;
        }
        __syncthreads();
        for (int off = 1; off < 2048; off <<= 1) {
            for (int i = t; i < 2048; i += 256)
                dst[i] = src[i] + (i >= off ? src[i-off] : 0);
            __syncthreads();
            int* tmp = src; src = dst; dst = tmp;
        }
        for (int u = t; u < NUU; u += 256) {
            int cnt, po;
            if (u < RELU_) {
                int dx = u/27, dy = u%27;
                cnt = hfun(dx)*hfun(dy);
                po  = cfun(dx)*196 + hfun(dx)*cfun(dy);
            } else if (u < RELU_ + NN) { cnt = 1; po = RELPAIRS + (u - RELU_); }
            else                       { cnt = 1; po = RELPAIRS + NN + (u - RELU_ - NN); }
            int eo = (u == 0) ? 0 : src[u-1];
            int j = 0;
            for (int s = 0; s < cnt; s += 16, j++) {
                int c = cnt - s; if (c > 16) c = 16;
                if (eo + j < WLMAX)
                    g_work[eo + j] = make_uint2((unsigned)(po + s),
                                                ((unsigned)u << 16) | (unsigned)c);
            }
        }
        if (t == 0) g_nwork = min(src[NUU-1], WLMAX);
        return;
    }

    // ---- LN + QK ----
    int n = bid - 153;
    int w = t >> 5, lane = t & 31;
    {
        const float* xr = x + ((size_t)(w*NN + n))*DIMV;
        float2 v = *(const float2*)(xr + 2*lane);
        float sum = v.x + v.y, sq = v.x*v.x + v.y*v.y;
        #pragma unroll
        for (int o = 16; o > 0; o >>= 1) {
            sum += __shfl_xor_sync(0xffffffffu, sum, o);
            sq  += __shfl_xor_sync(0xffffffffu, sq,  o);
        }
        float mu  = sum * (1.0f/DIMV);
        float var = sq  * (1.0f/DIMV) - mu*mu;
        float r   = rsqrtf(var + 1e-5f);
        float2 o2;
        o2.x = (v.x - mu) * r * gamma[2*lane]   + beta[2*lane];
        o2.y = (v.y - mu) * r * gamma[2*lane+1] + beta[2*lane+1];
        sm.ln.sxn[w][2*lane]   = o2.x;
        sm.ln.sxn[w][2*lane+1] = o2.y;
        *(float2*)(g_xn + ((size_t)(w*NN + n))*DIMV + 2*lane) = o2;
    }
    __syncthreads();
    int c = t & 127, half_ = t >> 7;
    float acc[BB];
    #pragma unroll
    for (int b = 0; b < BB; b++) acc[b] = 0.f;
    int d0 = half_ * 32;
    #pragma unroll 8
    for (int d = 0; d < 32; d++) {
        float wv = wqk[(d0 + d)*128 + c];
        #pragma unroll
        for (int b = 0; b < BB; b++) acc[b] += sm.ln.sxn[b][d0 + d] * wv;
    }
    #pragma unroll
    for (int b = 0; b < BB; b++) sm.ln.part[half_][c][b] = acc[b];
    __syncthreads();
    if (half_ == 0) {
        #pragma unroll
        for (int b = 0; b < BB; b++) {
            float v = sm.ln.part[0][c][b] + sm.ln.part[1][c][b];
            g_qk[((size_t)(b*NN + n))*128 + c] = v;
        }
    }
}

// ================= main kernel: attn [0,400) | pair GEMM [400,...) =============
__global__ void __launch_bounds__(256) k_mainattn(const float* __restrict__ up) {
    extern __shared__ __align__(16) char smx[];
    int bid = blockIdx.x;
    int tid = threadIdx.x, lane = tid & 31, w = tid >> 5;

    if (bid < NATTNBLK) {
        // ---------------- attention scores + softmax ----------------
        float* ks_s = (float*)smx;
        float* qs_s = ks_s + NN*33;
        float* red  = qs_s + DH;
        float* bc   = red + 8;
        int b  = bid / (NHEAD*25);
        int r  = bid % (NHEAD*25);
        int h  = r / 25;
        int nt = r % 25;
        for (int i = tid; i < NN*DH; i += 256) {
            int m = i >> 5, d = i & 31;
            ks_s[m*33 + d] = g_qk[(b*NN + m)*128 + 64 + h*DH + d];
        }
        __syncthreads();
        for (int k0 = 0; k0 < 8; k0++) {
            int n = nt*8 + k0;
            if (n >= NN) break;
            if (tid < DH) qs_s[tid] = g_qk[(b*NN + n)*128 + h*DH + tid];
            __syncthreads();
            float s = -3.0e38f;
            if (tid < NN) {
                float a = 0.f;
                #pragma unroll 8
                for (int d = 0; d < DH; d++) a += qs_s[d] * ks_s[tid*33 + d];
                s = a * SCALE;
            }
            float loc = s;
            #pragma unroll
            for (int o = 16; o > 0; o >>= 1) loc = fmaxf(loc, __shfl_xor_sync(0xffffffffu, loc, o));
            if (lane == 0) red[w] = loc;
            __syncthreads();
            if (tid == 0) {
                float m0 = red[0];
                #pragma unroll
                for (int i = 1; i < 8; i++) m0 = fmaxf(m0, red[i]);
                bc[0] = m0;
            }
            __syncthreads();
            float mx = bc[0];
            float p = (tid < NN) ? __expf(s - mx) : 0.f;
            float ls = p;
            #pragma unroll
            for (int o = 16; o > 0; o >>= 1) ls += __shfl_xor_sync(0xffffffffu, ls, o);
            if (lane == 0) red[w] = ls;
            __syncthreads();
            if (tid == 0) {
                float s0 = 0.f;
                #pragma unroll
                for (int i = 0; i < 8; i++) s0 += red[i];
                bc[0] = s0;
            }
            __syncthreads();
            float inv = 1.0f / bc[0];
            if (tid < NN) g_attn[(((size_t)b*NHEAD + h)*NN + n)*NN + tid] = p * inv;
            __syncthreads();
        }
        return;
    }

    // -------- pair GEMM: half-warp = 1 pair, lane = 4 e-cols, acc pairs e ------
    int wid_ = bid - NATTNBLK;
    if (wid_ >= g_nwork) return;
    uint2 wk = g_work[wid_];
    int pairStart = (int)wk.x;
    int u   = (int)(wk.y >> 16);
    int cnt = (int)(wk.y & 0xffffu);

    float* sU  = (float*)smx;                 // [64 d][64 e]
    float* sXT = sU + 4096;                   // [8 w][2 pr][64 d][8 b]

    const float* Up = up + (size_t)u * 4096;
    #pragma unroll
    for (int i = 0; i < 4; i++)
        *(float4*)&sU[tid*4 + i*1024] = *(const float4*)&Up[tid*4 + i*1024];

    // stage x transposed, conflict-free: lane = (b = l>>2, dl = l&3), d = dl+4i
    {
        int b = lane >> 2, dl = lane & 3;
        #pragma unroll
        for (int pr = 0; pr < 2; pr++) {
            int pp = 2*w + pr;
            if (pp < cnt) {
                unsigned pk = g_pairs[pairStart + pp];
                int m = (int)(pk & 0xffffu);
                const float* xr = g_xn + (b*NN + m)*DIMV;
                float* dst = sXT + ((w*2 + pr)*64)*8 + b;
                #pragma unroll
                for (int i = 0; i < 16; i++) {
                    int d = dl + 4*i;
                    dst[d*8] = xr[d];
                }
            }
        }
    }
    __syncthreads();

    int hw = lane >> 4, l16 = lane & 15;
    int e4 = l16 * 4;
    const float* xbase = sXT + ((w*2 + hw)*64)*8;
    const float* ubase = sU + e4;

    ull acc[8][2];
    #pragma unroll
    for (int b = 0; b < 8; b++) { acc[b][0] = 0ull; acc[b][1] = 0ull; }

    #pragma unroll 4
    for (int d = 0; d < 64; d++) {
        ulonglong2 uu = *(const ulonglong2*)(ubase + d*64);   // {u_e,u_e+1},{u_e+2,u_e+3}
        float4 xa = *(const float4*)(xbase + d*8);
        float4 xb = *(const float4*)(xbase + d*8 + 4);
        ull x0,x1,x2,x3,x4,x5,x6,x7;
        DUP2(x0, xa.x); DUP2(x1, xa.y); DUP2(x2, xa.z); DUP2(x3, xa.w);
        DUP2(x4, xb.x); DUP2(x5, xb.y); DUP2(x6, xb.z); DUP2(x7, xb.w);
        FMA2(acc[0][0], x0, uu.x); FMA2(acc[0][1], x0, uu.y);
        FMA2(acc[1][0], x1, uu.x); FMA2(acc[1][1], x1, uu.y);
        FMA2(acc[2][0], x2, uu.x); FMA2(acc[2][1], x2, uu.y);
        FMA2(acc[3][0], x3, uu.x); FMA2(acc[3][1], x3, uu.y);
        FMA2(acc[4][0], x4, uu.x); FMA2(acc[4][1], x4, uu.y);
        FMA2(acc[5][0], x5, uu.x); FMA2(acc[5][1], x5, uu.y);
        FMA2(acc[6][0], x6, uu.x); FMA2(acc[6][1], x6, uu.y);
        FMA2(acc[7][0], x7, uu.x); FMA2(acc[7][1], x7, uu.y);
    }

    int p = 2*w + hw;
    if (p < cnt) {
        unsigned pk = g_pairs[pairStart + p];
        int n = (int)(pk >> 16), m = (int)(pk & 0xffffu);
        size_t base = (size_t)(n*NN + m)*512 + e4;
        #pragma unroll
        for (int b = 0; b < 8; b++) {
            unsigned a0, a1, b0, b1;
            UNPK(a0, a1, acc[b][0]);
            UNPK(b0, b1, acc[b][1]);
            uint2 st;
            st.x = h2u(__floats2half2_rn(__uint_as_float(a0), __uint_as_float(a1)));
            st.y = h2u(__floats2half2_rn(__uint_as_float(b0), __uint_as_float(b1)));
            *(uint2*)&g_T[base + b*64] = st;
        }
    }
}

// ================= phase 2: attn-weighted sum + output projection ==============
__global__ void __launch_bounds__(256) k_out(const float* __restrict__ wout,
                                             const float* __restrict__ bout,
                                             float* __restrict__ out) {
    __shared__ float sA[2*200];
    __shared__ float2 sRed[8][32];
    __shared__ float sAcc[DIMV];
    int bid = blockIdx.x;
    int b = bid / NN, n = bid % NN;
    int t = threadIdx.x;
    int p = t & 31, q = t >> 5;
    for (int i = t; i < 2*NN; i += 256) {
        int h = i / NN, m = i % NN;
        sA[h*200 + m] = g_attn[(((size_t)b*NHEAD + h)*NN + n)*NN + m];
    }
    __syncthreads();
    int e = 2*p;
    int h = e >> 5;
    const __half2* Tb = (const __half2*)(g_T + (size_t)(n*NN)*(BB*DIMV) + b*DIMV + e);
    float2 acc; acc.x = 0.f; acc.y = 0.f;
    for (int m = q; m < NN; m += 8) {
        float a = sA[h*200 + m];
        float2 v = __half22float2(Tb[(size_t)m * (BB*DIMV/2)]);
        acc.x += a * v.x;
        acc.y += a * v.y;
    }
    sRed[q][p] = acc;
    __syncthreads();
    if (t < 32) {
        float2 s = sRed[0][t];
        #pragma unroll
        for (int j = 1; j < 8; j++) { s.x += sRed[j][t].x; s.y += sRed[j][t].y; }
        sAcc[2*t] = s.x; sAcc[2*t+1] = s.y;
    }
    __syncthreads();
    if (t < DIMV) {
        float r = bout[t];
        #pragma unroll 8
        for (int k = 0; k < DIMV; k++) r += sAcc[k] * wout[k*DIMV + t];
        out[((size_t)(b*NN + n))*DIMV + t] = r;
    }
}

// ---------------- launch -------------------------------------------------------
extern "C" void kernel_launch(void* const* d_in, const int* in_sizes, int n_in,
                              void* d_out, int out_size) {
    const float* x     = (const float*)d_in[0];
    const float* gamma = (const float*)d_in[1];
    const float* beta  = (const float*)d_in[2];
    const float* wqk   = (const float*)d_in[3];
    const float* up    = (const float*)d_in[4];
    const float* wout  = (const float*)d_in[5];
    const float* bout  = (const float*)d_in[6];
    float* out = (float*)d_out;

    cudaFuncSetAttribute(k_mainattn, cudaFuncAttributeMaxDynamicSharedMemorySize, SMEM_MAIN);

    k_setup   <<<153 + NN, 256>>>(x, gamma, beta, wqk);
    k_mainattn<<<NATTNBLK + WLMAX, 256, SMEM_MAIN>>>(up);
    k_out     <<<BB*NN, 256>>>(wout, bout, out);
}